// round 10
// baseline (speedup 1.0000x reference)
#include <cuda_runtime.h>
#include <math.h>

// Seq2Seq LSTM (D=256, H=1024, B=64, 3 layers, 64 enc + 64 dec steps), fp32.
// Single persistent kernel, 128 blocks, grid barrier between the 384 phases.

#define BATCH  64
#define HID    1024
#define FH     4096
#define DIN    256
#define TSTEPS 64
#define PRED   64
#define GRID   128
#define NTHR   256
#define KB     32
#define HH4    ((size_t)HID * FH)

__device__ float g_h[2][3][BATCH * HID];      // double-buffered hidden state (step parity)
__device__ float g_c[3][BATCH * HID];         // cell state (thread/block-local updates)
__device__ float g_outs[PRED * BATCH * HID];  // decoder top outputs [t][b][h]
__device__ unsigned g_barcnt = 0;
__device__ volatile unsigned g_bargen = 0;

struct Params {
    const float *x;
    const float *eWx0, *eWh0, *eWc0, *eb0;
    const float *eWx, *eWh, *eWc, *eb;
    const float *dWx, *dWh, *dWc, *db;
    const float *finW, *finb;
    const float *h0, *c0;
    float *out;
};

// Grid-wide barrier. All GRID blocks are co-resident (GRID <= SM count).
// __threadfence (scope gpu) on every thread flushes/orders L1 both sides.
__device__ __forceinline__ void gbar() {
    __threadfence();            // release: my writes visible device-wide
    __syncthreads();
    if (threadIdx.x == 0) {
        unsigned gen = g_bargen;
        if (atomicAdd(&g_barcnt, 1u) == GRID - 1) {
            atomicExch(&g_barcnt, 0u);
            __threadfence();
            g_bargen = gen + 1;
        } else {
            while (g_bargen == gen) { __nanosleep(40); }
        }
    }
    __syncthreads();
    __threadfence();            // acquire: invalidate L1 before cross-block reads
}

__device__ __forceinline__ float sigm(float x) { return 1.0f / (1.0f + expf(-x)); }

__global__ void __launch_bounds__(NTHR, 1) lstm_kernel(Params p) {
    __shared__ __align__(16) float As[2][64][36];
    __shared__ __align__(16) float Ws[2][32][34];
    __shared__ __align__(16) float Zx[64][33];

    const int bid = blockIdx.x;
    const int tid = threadIdx.x;

    // ---- init: broadcast h0/c0 over batch into parity-0 buffers ----
    for (int idx = bid * NTHR + tid; idx < 3 * BATCH * HID; idx += GRID * NTHR) {
        const int layer = idx / (BATCH * HID);
        const int rem   = idx - layer * (BATCH * HID);
        const int j     = rem & (HID - 1);
        g_h[0][layer][rem] = p.h0[layer * HID + j];
        g_c[layer][rem]    = p.c0[layer * HID + j];
    }
    gbar();

    // thread roles
    const int r0  = (tid >> 4) << 2;          // compute rows r0..r0+3
    const int tx  = tid & 15;                 // compute cols tx, tx+16 (of 32)
    const int ar0 = tid >> 3;                 // A-stage rows ar0, ar0+32
    const int ak4 = (tid & 7) * 4;            // A-stage k offset (float4)
    const int cc  = tid & 31;                 // W-stage tile column
    const int wk0 = tid >> 5;                 // W-stage k rows wk0 + {0,8,16,24}
    const int j0  = bid * 8;                  // this block's h-column base
    const int wcol = (cc >> 3) * HID + j0 + (cc & 7);  // gate-strided weight column

    // ---- 384 sequential cell phases ----
    #pragma unroll 1
    for (int sp = 0; sp < 3 * (TSTEPS + PRED); sp++) {
        const int step  = sp / 3;
        const int layer = sp - step * 3;
        const int pp    = step & 1;

        const float *A1, *W1, *W2, *bias, *Wc;
        int lda1, K1;
        const float *A2 = g_h[pp][layer];
        float *hout = g_h[pp ^ 1][layer];
        float *outp = nullptr;

        if (step < TSTEPS) {
            if (layer == 0) {
                A1 = p.x + (size_t)step * DIN; lda1 = TSTEPS * DIN; K1 = DIN;
                W1 = p.eWx0; W2 = p.eWh0; bias = p.eb0; Wc = p.eWc0;
            } else {
                A1 = g_h[pp ^ 1][layer - 1]; lda1 = HID; K1 = HID;
                W1 = p.eWx + (size_t)(layer - 1) * HH4;
                W2 = p.eWh + (size_t)(layer - 1) * HH4;
                bias = p.eb + (size_t)(layer - 1) * 4 * HID;
                Wc   = p.eWc + (size_t)(layer - 1) * 4 * HID;
            }
        } else {
            A1 = (layer == 0) ? g_h[pp][2] : g_h[pp ^ 1][layer - 1];
            lda1 = HID; K1 = HID;
            W1 = p.dWx + (size_t)layer * HH4;
            W2 = p.dWh + (size_t)layer * HH4;
            bias = p.db + (size_t)layer * 4 * HID;
            Wc   = p.dWc + (size_t)layer * 4 * HID;
            if (layer == 2) outp = g_outs + (size_t)(step - TSTEPS) * BATCH * HID;
        }

        const int nb1 = K1 / KB;
        const int nbt = nb1 + HID / KB;

        float a00 = 0.f, a01 = 0.f, a10 = 0.f, a11 = 0.f;
        float a20 = 0.f, a21 = 0.f, a30 = 0.f, a31 = 0.f;

        float4 ra0, ra1;
        float rw0, rw1, rw2, rw3;

#define LOADF(I) do {                                                          \
        const float *Ab; int lda; const float *Wb;                             \
        if ((I) < nb1) { Ab = A1 + (I) * KB; lda = lda1;                       \
                         Wb = W1 + (size_t)(I) * KB * FH + wcol; }             \
        else           { Ab = A2 + ((I) - nb1) * KB; lda = HID;                \
                         Wb = W2 + (size_t)((I) - nb1) * KB * FH + wcol; }     \
        ra0 = *(const float4 *)(Ab + ar0 * lda + ak4);                         \
        ra1 = *(const float4 *)(Ab + (ar0 + 32) * lda + ak4);                  \
        rw0 = Wb[(wk0 +  0) * FH]; rw1 = Wb[(wk0 +  8) * FH];                  \
        rw2 = Wb[(wk0 + 16) * FH]; rw3 = Wb[(wk0 + 24) * FH]; } while (0)

#define STOREF(B) do {                                                         \
        *(float4 *)&As[B][ar0][ak4]      = ra0;                                \
        *(float4 *)&As[B][ar0 + 32][ak4] = ra1;                                \
        Ws[B][cc][wk0 +  0] = rw0; Ws[B][cc][wk0 +  8] = rw1;                  \
        Ws[B][cc][wk0 + 16] = rw2; Ws[B][cc][wk0 + 24] = rw3; } while (0)

        int buf = 0;
        LOADF(0);
        STOREF(0);
        __syncthreads();

        #pragma unroll 1
        for (int i = 0; i < nbt; i++) {
            const bool more = (i + 1) < nbt;
            if (more) LOADF(i + 1);
            #pragma unroll
            for (int kp = 0; kp < KB; kp += 2) {
                float2 w0 = *(const float2 *)&Ws[buf][tx][kp];
                float2 w1 = *(const float2 *)&Ws[buf][tx + 16][kp];
                float2 v0 = *(const float2 *)&As[buf][r0 + 0][kp];
                float2 v1 = *(const float2 *)&As[buf][r0 + 1][kp];
                float2 v2 = *(const float2 *)&As[buf][r0 + 2][kp];
                float2 v3 = *(const float2 *)&As[buf][r0 + 3][kp];
                a00 += v0.x * w0.x; a00 += v0.y * w0.y;
                a01 += v0.x * w1.x; a01 += v0.y * w1.y;
                a10 += v1.x * w0.x; a10 += v1.y * w0.y;
                a11 += v1.x * w1.x; a11 += v1.y * w1.y;
                a20 += v2.x * w0.x; a20 += v2.y * w0.y;
                a21 += v2.x * w1.x; a21 += v2.y * w1.y;
                a30 += v3.x * w0.x; a30 += v3.y * w0.y;
                a31 += v3.x * w1.x; a31 += v3.y * w1.y;
            }
            if (more) { STOREF(buf ^ 1); __syncthreads(); buf ^= 1; }
        }

        // ---- fused gate epilogue over the block's [64 x 32] z-tile ----
        __syncthreads();   // all compute done before Zx reuse is read
        Zx[r0 + 0][tx] = a00; Zx[r0 + 0][tx + 16] = a01;
        Zx[r0 + 1][tx] = a10; Zx[r0 + 1][tx + 16] = a11;
        Zx[r0 + 2][tx] = a20; Zx[r0 + 2][tx + 16] = a21;
        Zx[r0 + 3][tx] = a30; Zx[r0 + 3][tx + 16] = a31;
        __syncthreads();

        float *cbuf = g_c[layer];
        #pragma unroll
        for (int e = 0; e < 2; e++) {
            const int idx = tid + e * NTHR;       // 0..511
            const int r = idx >> 3;               // batch row 0..63
            const int j = idx & 7;
            const int hc = j0 + j;
            const float cold = cbuf[r * HID + hc];
            const float zf = Zx[r][j]      + bias[hc]           + Wc[hc]           * cold;
            const float zi = Zx[r][8 + j]  + bias[HID + hc]     + Wc[HID + hc]     * cold;
            const float zg = Zx[r][16 + j] + bias[2 * HID + hc] + Wc[2 * HID + hc] * cold;
            const float zo = Zx[r][24 + j] + bias[3 * HID + hc] + Wc[3 * HID + hc] * cold;
            const float f  = sigm(zf);
            const float ii = sigm(zi);
            const float g  = tanhf(zg);
            const float o  = sigm(zo);
            const float cn = f * cold + ii * g;
            cbuf[r * HID + hc] = cn;
            const float hv = o * tanhf(cn);
            hout[r * HID + hc] = hv;
            if (outp) outp[r * HID + hc] = hv;
        }
        gbar();
    }

    // ---- final: sigmoid(outs @ finW + finb) -> out [pred*B, 256] ----
    {
        float *shA = &Zx[0][0];          // A tile [32][66]  (2112 floats)
        float *shW = &As[0][0][0];       // W tile [64][66]  (4224 of 4608 floats)
        const int row0 = bid * 32;       // rows of the 4096-row output
        const int r  = tid >> 3;         // 0..31
        const int dj = (tid & 7) * 8;    // 8 cols each

        #pragma unroll 1
        for (int ch = 0; ch < 4; ch++) {
            const int d0 = ch * 64;
            float fac[8];
            #pragma unroll
            for (int j = 0; j < 8; j++) fac[j] = 0.f;

            #pragma unroll 1
            for (int kb = 0; kb < HID; kb += 64) {
                __syncthreads();
                {   // stage A rows [row0..row0+32) x k[kb..kb+64)
                    const int rr = tid >> 3, kq = (tid & 7) * 8;
                    const float *src = g_outs + (size_t)(row0 + rr) * HID + kb + kq;
                    float4 v0 = *(const float4 *)src;
                    float4 v1 = *(const float4 *)(src + 4);
                    float *dst = shA + rr * 66 + kq;
                    dst[0] = v0.x; dst[1] = v0.y; dst[2] = v0.z; dst[3] = v0.w;
                    dst[4] = v1.x; dst[5] = v1.y; dst[6] = v1.z; dst[7] = v1.w;
                }
                {   // stage W rows k[kb..kb+64) x cols [d0..d0+64)
                    const int wr = tid >> 2, wq = (tid & 3) * 16;
                    const float *src = p.finW + (size_t)(kb + wr) * DIN + d0 + wq;
                    float4 u0 = *(const float4 *)(src + 0);
                    float4 u1 = *(const float4 *)(src + 4);
                    float4 u2 = *(const float4 *)(src + 8);
                    float4 u3 = *(const float4 *)(src + 12);
                    float *dst = shW + wr * 66 + wq;
                    dst[0]  = u0.x; dst[1]  = u0.y; dst[2]  = u0.z; dst[3]  = u0.w;
                    dst[4]  = u1.x; dst[5]  = u1.y; dst[6]  = u1.z; dst[7]  = u1.w;
                    dst[8]  = u2.x; dst[9]  = u2.y; dst[10] = u2.z; dst[11] = u2.w;
                    dst[12] = u3.x; dst[13] = u3.y; dst[14] = u3.z; dst[15] = u3.w;
                }
                __syncthreads();
                #pragma unroll 4
                for (int k = 0; k < 64; k++) {
                    const float a = shA[r * 66 + k];
                    const float *wrow = shW + k * 66 + dj;
                    float2 w01 = *(const float2 *)(wrow + 0);
                    float2 w23 = *(const float2 *)(wrow + 2);
                    float2 w45 = *(const float2 *)(wrow + 4);
                    float2 w67 = *(const float2 *)(wrow + 6);
                    fac[0] += a * w01.x; fac[1] += a * w01.y;
                    fac[2] += a * w23.x; fac[3] += a * w23.y;
                    fac[4] += a * w45.x; fac[5] += a * w45.y;
                    fac[6] += a * w67.x; fac[7] += a * w67.y;
                }
            }
            float *op = p.out + (size_t)(row0 + r) * DIN + d0 + dj;
            #pragma unroll
            for (int j = 0; j < 8; j++)
                op[j] = sigm(fac[j] + p.finb[d0 + dj + j]);
        }
    }
}

extern "C" void kernel_launch(void *const *d_in, const int *in_sizes, int n_in,
                              void *d_out, int out_size) {
    (void)in_sizes; (void)n_in; (void)out_size;
    Params p;
    p.x    = (const float *)d_in[0];
    p.eWx0 = (const float *)d_in[1];
    p.eWh0 = (const float *)d_in[2];
    p.eWc0 = (const float *)d_in[3];
    p.eb0  = (const float *)d_in[4];
    p.eWx  = (const float *)d_in[5];
    p.eWh  = (const float *)d_in[6];
    p.eWc  = (const float *)d_in[7];
    p.eb   = (const float *)d_in[8];
    p.dWx  = (const float *)d_in[9];
    p.dWh  = (const float *)d_in[10];
    p.dWc  = (const float *)d_in[11];
    p.db   = (const float *)d_in[12];
    p.finW = (const float *)d_in[13];
    p.finb = (const float *)d_in[14];
    p.h0   = (const float *)d_in[15];
    p.c0   = (const float *)d_in[16];
    p.out  = (float *)d_out;
    lstm_kernel<<<GRID, NTHR>>>(p);
}

// round 11
// speedup vs baseline: 1.3186x; 1.3186x over previous
#include <cuda_runtime.h>
#include <math.h>

// Seq2Seq LSTM (D=256, H=1024, B=64, 3 layers, 64 enc + 64 dec steps), fp32.
// Persistent kernel, 128 blocks x 512 threads, grid barrier between phases.
// 4 intra-block k-splits (named barriers), packed fma.rn.f32x2 inner loop.

#define BATCH  64
#define HID    1024
#define FH     4096
#define DIN    256
#define TSTEPS 64
#define PRED   64
#define GRID   128
#define NTHR   512
#define SPLITS 4
#define TPS    128
#define KB     32
#define HH4    ((size_t)HID * FH)

typedef unsigned long long ull;

__device__ float g_h[2][3][BATCH * HID];      // double-buffered hidden state
__device__ float g_c[3][BATCH * HID];         // cell state
__device__ float g_outs[PRED * BATCH * HID];  // decoder top outputs [t][b][h]
__device__ unsigned g_barcnt = 0;
__device__ volatile unsigned g_bargen = 0;

struct Params {
    const float *x;
    const float *eWx0, *eWh0, *eWc0, *eb0;
    const float *eWx, *eWh, *eWc, *eb;
    const float *dWx, *dWh, *dWc, *db;
    const float *finW, *finb;
    const float *h0, *c0;
    float *out;
};

__device__ __forceinline__ void gbar() {
    __threadfence();
    __syncthreads();
    if (threadIdx.x == 0) {
        unsigned gen = g_bargen;
        if (atomicAdd(&g_barcnt, 1u) == GRID - 1) {
            atomicExch(&g_barcnt, 0u);
            __threadfence();
            g_bargen = gen + 1;
        } else {
            while (g_bargen == gen) { __nanosleep(32); }
        }
    }
    __syncthreads();
    __threadfence();
}

__device__ __forceinline__ float sigm(float x) { return 1.0f / (1.0f + expf(-x)); }

__device__ __forceinline__ void barsplit(int id) {
    asm volatile("bar.sync %0, %1;" :: "r"(id), "r"(TPS) : "memory");
}

#define FMA2(acc, a, w) \
    asm volatile("fma.rn.f32x2 %0, %1, %2, %0;" : "+l"(acc) : "l"(a), "l"(w))

__device__ __forceinline__ float pairsum(ull v) {
    float lo, hi;
    asm("mov.b64 {%0, %1}, %2;" : "=f"(lo), "=f"(hi) : "l"(v));
    return lo + hi;
}

// dynamic smem layout (floats):
//   As: [4 splits][2 buf][64 rows][36]   = 18432
//   Ws: [4 splits][2 buf][32 cols][34]   =  8704
//   Zx: [4 splits][64 rows][33]          =  8448
#define AS_OFF 0
#define WS_OFF 18432
#define ZX_OFF (18432 + 8704)
#define SMEM_FLOATS (18432 + 8704 + 8448)
#define AS(s,b,row,k) smAs[((((s)*2+(b))*64 + (row))*36) + (k)]
#define WS(s,b,col,k) smWs[((((s)*2+(b))*32 + (col))*34) + (k)]
#define ZX(s,row,col) smZx[(((s)*64 + (row))*33) + (col)]

__global__ void __launch_bounds__(NTHR, 1) lstm_kernel(Params p) {
    extern __shared__ float smdyn[];
    float *smAs = smdyn + AS_OFF;
    float *smWs = smdyn + WS_OFF;
    float *smZx = smdyn + ZX_OFF;

    const int bid = blockIdx.x;
    const int tid = threadIdx.x;

    // ---- init: broadcast h0/c0 over batch into parity-0 buffers ----
    for (int idx = bid * NTHR + tid; idx < 3 * BATCH * HID; idx += GRID * NTHR) {
        const int layer = idx / (BATCH * HID);
        const int rem   = idx - layer * (BATCH * HID);
        const int j     = rem & (HID - 1);
        g_h[0][layer][rem] = p.h0[layer * HID + j];
        g_c[layer][rem]    = p.c0[layer * HID + j];
    }
    gbar();

    // thread roles
    const int split = tid >> 7;               // 0..3
    const int ts    = tid & (TPS - 1);        // 0..127 within split
    const int rbase = (ts >> 3) * 4;          // compute rows rbase..rbase+3
    const int cg    = ts & 7;                 // compute cols cg + 8*gate
    const int cc    = ts & 31;                // W-stage tile column
    const int kqw   = (ts >> 5) * 8;          // W-stage k offset (8 rows)
    const int j0    = bid * 8;                // block's h-column base
    const size_t wcol = (size_t)(cc >> 3) * HID + j0 + (cc & 7);

    // ---- 384 sequential cell phases ----
    #pragma unroll 1
    for (int sp = 0; sp < 3 * (TSTEPS + PRED); sp++) {
        const int step  = sp / 3;
        const int layer = sp - step * 3;
        const int pp    = step & 1;

        const float *A1, *W1, *W2, *bias, *Wc;
        int lda1, K1;
        const float *A2 = g_h[pp][layer];
        float *hout = g_h[pp ^ 1][layer];
        float *outp = nullptr;

        if (step < TSTEPS) {
            if (layer == 0) {
                A1 = p.x + (size_t)step * DIN; lda1 = TSTEPS * DIN; K1 = DIN;
                W1 = p.eWx0; W2 = p.eWh0; bias = p.eb0; Wc = p.eWc0;
            } else {
                A1 = g_h[pp ^ 1][layer - 1]; lda1 = HID; K1 = HID;
                W1 = p.eWx + (size_t)(layer - 1) * HH4;
                W2 = p.eWh + (size_t)(layer - 1) * HH4;
                bias = p.eb + (size_t)(layer - 1) * 4 * HID;
                Wc   = p.eWc + (size_t)(layer - 1) * 4 * HID;
            }
        } else {
            A1 = (layer == 0) ? g_h[pp][2] : g_h[pp ^ 1][layer - 1];
            lda1 = HID; K1 = HID;
            W1 = p.dWx + (size_t)layer * HH4;
            W2 = p.dWh + (size_t)layer * HH4;
            bias = p.db + (size_t)layer * 4 * HID;
            Wc   = p.dWc + (size_t)layer * 4 * HID;
            if (layer == 2) outp = g_outs + (size_t)(step - TSTEPS) * BATCH * HID;
        }

        const int nb1 = K1 / KB;
        const int nbt = nb1 + HID / KB;
        const int per = nbt / SPLITS;
        const int i0  = split * per;

        ull acc[4][4];
        #pragma unroll
        for (int r = 0; r < 4; r++)
            #pragma unroll
            for (int g = 0; g < 4; g++) acc[r][g] = 0ULL;

        float4 ra[4];
        float  rw[8];

#define LOADBLK(I) do {                                                         \
        const float *Ab; int lda; const float *Wb;                              \
        if ((I) < nb1) { Ab = A1 + (size_t)(I) * KB; lda = lda1;                \
                         Wb = W1 + (size_t)(I) * KB * FH; }                     \
        else           { Ab = A2 + ((I) - nb1) * KB; lda = HID;                 \
                         Wb = W2 + (size_t)((I) - nb1) * KB * FH; }             \
        _Pragma("unroll")                                                       \
        for (int it = 0; it < 4; it++) {                                        \
            const int flat = ts + it * TPS;                                     \
            const int row = flat >> 3, kq = (flat & 7) * 4;                     \
            ra[it] = *(const float4 *)(Ab + (size_t)row * lda + kq);            \
        }                                                                       \
        const float *Wp = Wb + (size_t)kqw * FH + wcol;                         \
        _Pragma("unroll")                                                       \
        for (int i2 = 0; i2 < 8; i2++) rw[i2] = Wp[(size_t)i2 * FH];            \
    } while (0)

#define STOREBLK(B) do {                                                        \
        _Pragma("unroll")                                                       \
        for (int it = 0; it < 4; it++) {                                        \
            const int flat = ts + it * TPS;                                     \
            const int row = flat >> 3, kq = (flat & 7) * 4;                     \
            *(float4 *)&AS(split, B, row, kq) = ra[it];                         \
        }                                                                       \
        _Pragma("unroll")                                                       \
        for (int i2 = 0; i2 < 8; i2++) WS(split, B, cc, kqw + i2) = rw[i2];     \
    } while (0)

        int buf = 0;
        LOADBLK(i0);
        STOREBLK(0);
        barsplit(1 + split);

        #pragma unroll 1
        for (int i = i0; i < i0 + per; i++) {
            const bool more = (i + 1) < (i0 + per);
            if (more) LOADBLK(i + 1);
            #pragma unroll
            for (int kp = 0; kp < KB; kp += 4) {
                ulonglong2 av[4];
                #pragma unroll
                for (int r = 0; r < 4; r++)
                    av[r] = *(const ulonglong2 *)&AS(split, buf, rbase + r, kp);
                #pragma unroll
                for (int g = 0; g < 4; g++) {
                    const ull w0 = *(const ull *)&WS(split, buf, 8 * g + cg, kp);
                    const ull w1 = *(const ull *)&WS(split, buf, 8 * g + cg, kp + 2);
                    #pragma unroll
                    for (int r = 0; r < 4; r++) {
                        FMA2(acc[r][g], av[r].x, w0);
                        FMA2(acc[r][g], av[r].y, w1);
                    }
                }
            }
            if (more) { STOREBLK(buf ^ 1); barsplit(1 + split); buf ^= 1; }
        }

        // ---- split partials -> Zx exchange ----
        #pragma unroll
        for (int r = 0; r < 4; r++)
            #pragma unroll
            for (int g = 0; g < 4; g++)
                ZX(split, rbase + r, 8 * g + cg) = pairsum(acc[r][g]);
        __syncthreads();

        // ---- fused gate epilogue: 512 threads, 512 (row, hcol) elements ----
        {
            const int r  = tid >> 3;
            const int jj = tid & 7;
            const int hc = j0 + jj;
            float zf = 0.f, zi = 0.f, zg = 0.f, zo = 0.f;
            #pragma unroll
            for (int s = 0; s < SPLITS; s++) {
                zf += ZX(s, r, jj);
                zi += ZX(s, r, 8 + jj);
                zg += ZX(s, r, 16 + jj);
                zo += ZX(s, r, 24 + jj);
            }
            float *cbuf = g_c[layer];
            const float cold = cbuf[r * HID + hc];
            zf += bias[hc]           + Wc[hc]           * cold;
            zi += bias[HID + hc]     + Wc[HID + hc]     * cold;
            zg += bias[2 * HID + hc] + Wc[2 * HID + hc] * cold;
            zo += bias[3 * HID + hc] + Wc[3 * HID + hc] * cold;
            const float f  = sigm(zf);
            const float ii = sigm(zi);
            const float g  = tanhf(zg);
            const float o  = sigm(zo);
            const float cn = f * cold + ii * g;
            cbuf[r * HID + hc] = cn;
            const float hv = o * tanhf(cn);
            hout[r * HID + hc] = hv;
            if (outp) outp[r * HID + hc] = hv;
        }
        gbar();
    }

    // ---- final: sigmoid(outs @ finW + finb) -> out [4096, 256] ----
    {
        float *shA = smdyn;               // [32][68]
        float *shW = smdyn + 32 * 68;     // [64][68]
        const int row0 = bid * 32;
        const int r  = tid >> 4;          // 0..31
        const int dj = (tid & 15) * 4;    // 0..60

        #pragma unroll 1
        for (int ch = 0; ch < 4; ch++) {
            const int d0 = ch * 64;
            float f0 = 0.f, f1 = 0.f, f2 = 0.f, f3 = 0.f;

            #pragma unroll 1
            for (int kb = 0; kb < HID; kb += 64) {
                __syncthreads();
                {   // stage A: rows [row0, row0+32) x k [kb, kb+64)
                    const int ar = tid >> 4, akq = (tid & 15) * 4;
                    *(float4 *)&shA[ar * 68 + akq] =
                        *(const float4 *)&g_outs[(size_t)(row0 + ar) * HID + kb + akq];
                }
                {   // stage W: k rows [kb, kb+64) x cols [d0, d0+64)
                    const int wr = tid >> 3, wq = (tid & 7) * 8;
                    const float *src = p.finW + (size_t)(kb + wr) * DIN + d0 + wq;
                    float4 u0 = *(const float4 *)src;
                    float4 u1 = *(const float4 *)(src + 4);
                    *(float4 *)&shW[wr * 68 + wq]     = u0;
                    *(float4 *)&shW[wr * 68 + wq + 4] = u1;
                }
                __syncthreads();
                #pragma unroll 8
                for (int k = 0; k < 64; k++) {
                    const float a = shA[r * 68 + k];
                    const float4 w = *(const float4 *)&shW[k * 68 + dj];
                    f0 += a * w.x; f1 += a * w.y; f2 += a * w.z; f3 += a * w.w;
                }
            }
            float *op = p.out + (size_t)(row0 + r) * DIN + d0 + dj;
            op[0] = sigm(f0 + p.finb[d0 + dj + 0]);
            op[1] = sigm(f1 + p.finb[d0 + dj + 1]);
            op[2] = sigm(f2 + p.finb[d0 + dj + 2]);
            op[3] = sigm(f3 + p.finb[d0 + dj + 3]);
        }
    }
}

extern "C" void kernel_launch(void *const *d_in, const int *in_sizes, int n_in,
                              void *d_out, int out_size) {
    (void)in_sizes; (void)n_in; (void)out_size;
    Params p;
    p.x    = (const float *)d_in[0];
    p.eWx0 = (const float *)d_in[1];
    p.eWh0 = (const float *)d_in[2];
    p.eWc0 = (const float *)d_in[3];
    p.eb0  = (const float *)d_in[4];
    p.eWx  = (const float *)d_in[5];
    p.eWh  = (const float *)d_in[6];
    p.eWc  = (const float *)d_in[7];
    p.eb   = (const float *)d_in[8];
    p.dWx  = (const float *)d_in[9];
    p.dWh  = (const float *)d_in[10];
    p.dWc  = (const float *)d_in[11];
    p.db   = (const float *)d_in[12];
    p.finW = (const float *)d_in[13];
    p.finb = (const float *)d_in[14];
    p.h0   = (const float *)d_in[15];
    p.c0   = (const float *)d_in[16];
    p.out  = (float *)d_out;

    const int smem_bytes = SMEM_FLOATS * 4;
    cudaFuncSetAttribute(lstm_kernel,
                         cudaFuncAttributeMaxDynamicSharedMemorySize, smem_bytes);
    lstm_kernel<<<GRID, NTHR, smem_bytes>>>(p);
}

// round 14
// speedup vs baseline: 2.3252x; 1.7633x over previous
#include <cuda_runtime.h>
#include <cuda_bf16.h>
#include <math.h>

// Seq2Seq LSTM (D=256, H=1024, B=64, 3 layers, 64 enc + 64 dec steps).
// bf16 hi/lo-split mma.sync (HMMA) implementation for plain sm_103 target.
// conv_kernel: fp32 -> bf16 hi/lo weight transpose/split (+x split, h0/c0 init).
// lstm_kernel: persistent, 128 CTAs x 256 thr, grid barrier between 384 phases.

#define BATCH  64
#define HID    1024
#define FH     4096
#define DIN    256
#define TSTEPS 64
#define PRED   64
#define GRID   128
#define NTHR   256

typedef unsigned int u32;
typedef unsigned long long u64;

// ---------------- static device buffers (no allocation) ----------------
#define WT_ELEMS 47185920ull   // 4096 * (1280 + 5*2048)
__device__ __align__(256) __nv_bfloat16 g_wth[WT_ELEMS];
__device__ __align__(256) __nv_bfloat16 g_wtl[WT_ELEMS];
__device__ __align__(256) __nv_bfloat16 g_xh[TSTEPS * BATCH * DIN];
__device__ __align__(256) __nv_bfloat16 g_xl[TSTEPS * BATCH * DIN];
__device__ __align__(256) __nv_bfloat16 g_hh[2 * 3 * BATCH * HID];
__device__ __align__(256) __nv_bfloat16 g_hl[2 * 3 * BATCH * HID];
__device__ __align__(256) float g_c[3 * BATCH * HID];
__device__ __align__(256) float g_outs[PRED * BATCH * HID];
__device__ unsigned g_barcnt = 0;
__device__ volatile unsigned g_bargen = 0;

struct Params {
    const float *x;
    const float *eWx0, *eWh0, *eWc0, *eb0;
    const float *eWx, *eWh, *eWc, *eb;
    const float *dWx, *dWh, *dWc, *db;
    const float *finW, *finb;
    const float *h0, *c0;
    float *out;
};

// ---------------- helpers ----------------
__device__ __forceinline__ u32 smem_u32(const void *p) {
    u32 a;
    asm("{ .reg .u64 t; cvta.to.shared.u64 t, %1; cvt.u32.u64 %0, t; }" : "=r"(a) : "l"(p));
    return a;
}

__device__ __forceinline__ void ldsm4(u32 *r, u32 a) {
    asm volatile("ldmatrix.sync.aligned.m8n8.x4.shared.b16 {%0,%1,%2,%3}, [%4];"
        : "=r"(r[0]), "=r"(r[1]), "=r"(r[2]), "=r"(r[3]) : "r"(a));
}

__device__ __forceinline__ void mma16816(float *d, const u32 *a, const u32 *b) {
    asm("mma.sync.aligned.m16n8k16.row.col.f32.bf16.bf16.f32 "
        "{%0,%1,%2,%3}, {%4,%5,%6,%7}, {%8,%9}, {%0,%1,%2,%3};"
        : "+f"(d[0]), "+f"(d[1]), "+f"(d[2]), "+f"(d[3])
        : "r"(a[0]), "r"(a[1]), "r"(a[2]), "r"(a[3]), "r"(b[0]), "r"(b[1]));
}

__device__ __forceinline__ void gbar() {
    __threadfence();
    __syncthreads();
    if (threadIdx.x == 0) {
        unsigned gen = g_bargen;
        if (atomicAdd(&g_barcnt, 1u) == GRID - 1) {
            atomicExch(&g_barcnt, 0u);
            __threadfence();
            g_bargen = gen + 1;
        } else {
            while (g_bargen == gen) { __nanosleep(32); }
        }
    }
    __syncthreads();
    __threadfence();
}

__device__ __forceinline__ float sigm(float x) { return 1.0f / (1.0f + expf(-x)); }

// ---------------- conversion kernel ----------------
// Weight column mapping: global n (0..4095) -> oc = gate*1024 + hcol,
//   gate = (n>>3)&3, hcol = (n>>5)*8 + (n&7)   (CTA bid owns n = bid*32 .. +31)
// Storage: w[n][k] K-contiguous, per class offset offW.
#define WT_ITEMS 5898240u
#define X_ITEMS  131072u
#define H0_ITEMS 24576u

__global__ void conv_kernel(Params p) {
    const u32 id = blockIdx.x * 256u + threadIdx.x;
    if (id < WT_ITEMS) {
        u32 cls, q;
        if (id < 655360u) { cls = 0; q = id; }
        else { u32 t2 = id - 655360u; cls = 1 + (t2 >> 20); q = t2 & 0xFFFFFu; }
        const u32 n  = q & 4095u;
        const u32 k  = (q >> 12) * 8;
        const int Kc = (cls == 0) ? 1280 : 2048;
        const int K1 = (cls == 0) ? 256 : 1024;
        const float *W1, *W2;
        if (cls == 0)      { W1 = p.eWx0; W2 = p.eWh0; }
        else if (cls <= 2) { W1 = p.eWx + (size_t)(cls - 1) * HID * FH;
                             W2 = p.eWh + (size_t)(cls - 1) * HID * FH; }
        else               { W1 = p.dWx + (size_t)(cls - 3) * HID * FH;
                             W2 = p.dWh + (size_t)(cls - 3) * HID * FH; }
        const u32 oc = ((n >> 3) & 3u) * 1024u + (n >> 5) * 8u + (n & 7u);
        u64 offW = (cls == 0) ? 0ull
                 : 4096ull * 1280ull + (u64)(cls - 1) * 4096ull * 2048ull;
        __align__(16) __nv_bfloat16 hh[8], ll[8];
        #pragma unroll
        for (int kk = 0; kk < 8; kk++) {
            const int kr = (int)k + kk;
            const float v = (kr < K1) ? W1[(size_t)kr * FH + oc]
                                      : W2[(size_t)(kr - K1) * FH + oc];
            __nv_bfloat16 h = __float2bfloat16(v);
            hh[kk] = h;
            ll[kk] = __float2bfloat16(v - __bfloat162float(h));
        }
        const u64 o = offW + (u64)n * Kc + k;
        *(uint4 *)&g_wth[o] = *(const uint4 *)hh;
        *(uint4 *)&g_wtl[o] = *(const uint4 *)ll;
    } else if (id < WT_ITEMS + X_ITEMS) {
        const u32 q = id - WT_ITEMS;
        const u32 d8 = q & 31u;
        const u32 b = (q >> 5) & 63u;
        const u32 t = q >> 11;
        const float *src = p.x + ((size_t)b * TSTEPS + t) * DIN + d8 * 8;
        __align__(16) __nv_bfloat16 hh[8], ll[8];
        #pragma unroll
        for (int kk = 0; kk < 8; kk++) {
            const float v = src[kk];
            __nv_bfloat16 h = __float2bfloat16(v);
            hh[kk] = h;
            ll[kk] = __float2bfloat16(v - __bfloat162float(h));
        }
        const size_t o = ((size_t)t * BATCH + b) * DIN + d8 * 8;
        *(uint4 *)&g_xh[o] = *(const uint4 *)hh;
        *(uint4 *)&g_xl[o] = *(const uint4 *)ll;
    } else if (id < WT_ITEMS + X_ITEMS + H0_ITEMS) {
        const u32 q = id - WT_ITEMS - X_ITEMS;
        const u32 j8 = q & 127u;
        const u32 b = (q >> 7) & 63u;
        const u32 l = q >> 13;
        __align__(16) __nv_bfloat16 hh[8], ll[8];
        #pragma unroll
        for (int kk = 0; kk < 8; kk++) {
            const float v = p.h0[l * HID + j8 * 8 + kk];
            __nv_bfloat16 h = __float2bfloat16(v);
            hh[kk] = h;
            ll[kk] = __float2bfloat16(v - __bfloat162float(h));
        }
        const size_t o = ((size_t)l * BATCH + b) * HID + j8 * 8;   // parity 0
        *(uint4 *)&g_hh[o] = *(const uint4 *)hh;
        *(uint4 *)&g_hl[o] = *(const uint4 *)ll;
    } else if (id < WT_ITEMS + X_ITEMS + 2 * H0_ITEMS) {
        const u32 q = id - WT_ITEMS - X_ITEMS - H0_ITEMS;
        const u32 j8 = q & 127u;
        const u32 b = (q >> 7) & 63u;
        const u32 l = q >> 13;
        float4 v0 = *(const float4 *)&p.c0[l * HID + j8 * 8];
        float4 v1 = *(const float4 *)&p.c0[l * HID + j8 * 8 + 4];
        float *dst = &g_c[((size_t)l * BATCH + b) * HID + j8 * 8];
        *(float4 *)dst = v0;
        *(float4 *)(dst + 4) = v1;
    }
}

// ---------------- main persistent kernel ----------------
// SMEM per buffer: A [128 rows][136 bf16] (272 B row stride) = 34816 B,
//                  B [64][136] = 17408 B.  Two buffers (double-buffered).
#define RS        272
#define OFF_B     34816u
#define BUFSTRIDE 52224u
#define SMEM_REQ  (2 * 52224 + 1024)

__global__ void __launch_bounds__(NTHR, 1) lstm_kernel(Params p) {
    extern __shared__ char smraw[];
    const u32 sb0 = smem_u32(smraw);
    const u32 sb = (sb0 + 1023u) & ~1023u;
    char *smc = smraw + (sb - sb0);

    const int tid = threadIdx.x;
    const int wid = tid >> 5;
    const int lane = tid & 31;
    const int bid = blockIdx.x;

    const int grp = wid >> 2;     // k-group 0/1
    const int wm  = wid & 3;      // m-warp: rows 32*wm .. +31
    const u32 aoff = (u32)(lane & 15) * RS + (u32)(lane >> 4) * 16u;
    const u32 boff = (u32)(((lane >> 4) << 3) + (lane & 7)) * RS
                   + (u32)((lane >> 3) & 1) * 16u;
    const int j0 = bid * 8;       // this CTA's h-column base
    const int n0 = bid * 32;      // this CTA's weight-column base

    gbar();   // conv_kernel completed (stream-ordered) + inter-replay state reset

    #pragma unroll 1
    for (int sp = 0; sp < 3 * (TSTEPS + PRED); sp++) {
        const int step = sp / 3;
        const int layer = sp - step * 3;
        const int pp = step & 1;
        const int cls = (step < TSTEPS) ? layer : 3 + layer;
        const int Kc  = (cls == 0) ? 1280 : 2048;
        const int nb1 = (cls == 0) ? 2 : 8;
        const int nc  = Kc / 128;

        const __nv_bfloat16 *a1h, *a1l;
        int lda1;
        if (step < TSTEPS && layer == 0) {
            a1h = g_xh + (size_t)step * BATCH * DIN;
            a1l = g_xl + (size_t)step * BATCH * DIN;
            lda1 = DIN;
        } else {
            const int src = (step >= TSTEPS && layer == 0) ? (pp * 3 + 2)
                                                           : ((pp ^ 1) * 3 + layer - 1);
            a1h = g_hh + (size_t)src * BATCH * HID;
            a1l = g_hl + (size_t)src * BATCH * HID;
            lda1 = HID;
        }
        const __nv_bfloat16 *a2h = g_hh + (size_t)(pp * 3 + layer) * BATCH * HID;
        const __nv_bfloat16 *a2l = g_hl + (size_t)(pp * 3 + layer) * BATCH * HID;

        u64 offW = (cls == 0) ? 0ull
                 : 4096ull * 1280ull + (u64)(cls - 1) * 4096ull * 2048ull;
        const __nv_bfloat16 *wh = g_wth + offW + (u64)n0 * Kc;
        const __nv_bfloat16 *wl = g_wtl + offW + (u64)n0 * Kc;

        const float *bias, *Wc;
        if (step < TSTEPS) {
            if (layer == 0) { bias = p.eb0; Wc = p.eWc0; }
            else { bias = p.eb + (size_t)(layer - 1) * 4 * HID;
                   Wc = p.eWc + (size_t)(layer - 1) * 4 * HID; }
        } else {
            bias = p.db + (size_t)layer * 4 * HID;
            Wc = p.dWc + (size_t)layer * 4 * HID;
        }

        float acc[2][8][4];
        #pragma unroll
        for (int mi = 0; mi < 2; mi++)
            #pragma unroll
            for (int nt = 0; nt < 8; nt++)
                #pragma unroll
                for (int q = 0; q < 4; q++) acc[mi][nt][q] = 0.f;

        uint4 ra[8], rb[4];

#define LOADCHUNK(C) do {                                                       \
        const __nv_bfloat16 *sh_, *sl_; int lda_, krel_;                        \
        if ((C) < nb1) { sh_ = a1h; sl_ = a1l; lda_ = lda1; krel_ = (C) * 128; }\
        else { sh_ = a2h; sl_ = a2l; lda_ = HID; krel_ = ((C) - nb1) * 128; }   \
        _Pragma("unroll")                                                       \
        for (int i_ = 0; i_ < 8; i_++) {                                        \
            const int flat_ = i_ * NTHR + tid;                                  \
            const int row_ = flat_ >> 4, kq_ = (flat_ & 15) * 8;                \
            ra[i_] = *(const uint4 *)(((row_ < 64) ? sh_ : sl_)                 \
                        + (size_t)(row_ & 63) * lda_ + krel_ + kq_);            \
        }                                                                       \
        _Pragma("unroll")                                                       \
        for (int i_ = 0; i_ < 4; i_++) {                                        \
            const int flat_ = i_ * NTHR + tid;                                  \
            const int row_ = flat_ >> 4, kq_ = (flat_ & 15) * 8;                \
            const __nv_bfloat16 *ws_ = (row_ < 32)                              \
                ? (wh + (size_t)row_ * Kc) : (wl + (size_t)(row_ - 32) * Kc);   \
            rb[i_] = *(const uint4 *)(ws_ + (size_t)(C) * 128 + kq_);           \
        }                                                                       \
    } while (0)

#define STORECHUNK(B_) do {                                                     \
        char *bb_ = smc + (u32)(B_) * BUFSTRIDE;                                \
        _Pragma("unroll")                                                       \
        for (int i_ = 0; i_ < 8; i_++) {                                        \
            const int flat_ = i_ * NTHR + tid;                                  \
            const int row_ = flat_ >> 4, kq_ = (flat_ & 15) * 8;                \
            *(uint4 *)(bb_ + row_ * RS + kq_ * 2) = ra[i_];                     \
        }                                                                       \
        _Pragma("unroll")                                                       \
        for (int i_ = 0; i_ < 4; i_++) {                                        \
            const int flat_ = i_ * NTHR + tid;                                  \
            const int row_ = flat_ >> 4, kq_ = (flat_ & 15) * 8;                \
            *(uint4 *)(bb_ + OFF_B + row_ * RS + kq_ * 2) = rb[i_];             \
        }                                                                       \
    } while (0)

        LOADCHUNK(0);
        STORECHUNK(0);
        __syncthreads();

        #pragma unroll 1
        for (int c = 0; c < nc; c++) {
            const bool more = (c + 1) < nc;
            if (more) LOADCHUNK(c + 1);
            const u32 smb = sb + (u32)(c & 1) * BUFSTRIDE;
            const u32 ab = smb + aoff + (u32)wm * 8704u;
            const u32 bb = smb + OFF_B + boff;
            #pragma unroll
            for (int ks = 0; ks < 4; ks++) {
                const u32 kk = (u32)(grp * 4 + ks) * 32u;
                u32 af[2][4];
                ldsm4(af[0], ab + kk);
                ldsm4(af[1], ab + 4352u + kk);
                u32 bf[4][4];
                #pragma unroll
                for (int np = 0; np < 4; np++)
                    ldsm4(bf[np], bb + (u32)np * 4352u + kk);
                #pragma unroll
                for (int mi = 0; mi < 2; mi++)
                    #pragma unroll
                    for (int nt = 0; nt < 8; nt++)
                        mma16816(acc[mi][nt], af[mi], &bf[nt >> 1][(nt & 1) * 2]);
            }
            if (more) { __syncthreads(); STORECHUNK((c + 1) & 1); __syncthreads(); }
        }

        // ---- dump accumulators (per k-group) to smem Z ----
        __syncthreads();
        float *Z0 = (float *)smc;
        float *Zg = Z0 + (size_t)grp * 128 * 66;
        #pragma unroll
        for (int mi = 0; mi < 2; mi++) {
            const int row = wm * 32 + mi * 16 + (lane >> 2);
            #pragma unroll
            for (int nt = 0; nt < 8; nt++) {
                const int col = nt * 8 + (lane & 3) * 2;
                *(float2 *)&Zg[row * 66 + col] =
                    make_float2(acc[mi][nt][0], acc[mi][nt][1]);
                *(float2 *)&Zg[(row + 8) * 66 + col] =
                    make_float2(acc[mi][nt][2], acc[mi][nt][3]);
            }
        }
        __syncthreads();

        // ---- fused gate epilogue: 512 (row, hcol) items over 256 threads ----
        {
            float *Z1 = Z0 + 128 * 66;
            float *hout_h = (float *)nullptr;
            __nv_bfloat16 *hhp_base = g_hh + (size_t)((pp ^ 1) * 3 + layer) * BATCH * HID;
            __nv_bfloat16 *hlp_base = g_hl + (size_t)((pp ^ 1) * 3 + layer) * BATCH * HID;
            float *cb_base = g_c + (size_t)layer * BATCH * HID;
            float *out_base = (step >= TSTEPS && layer == 2)
                ? g_outs + (size_t)(step - TSTEPS) * BATCH * HID : nullptr;
            (void)hout_h;
            #pragma unroll
            for (int it = 0; it < 2; it++) {
                const int idx = tid + it * NTHR;
                const int r = idx >> 3;
                const int jj = idx & 7;
                const int hc = j0 + jj;
                float z[4];
                #pragma unroll
                for (int g = 0; g < 4; g++) {
                    const int nh = g * 8 + jj, nl = 32 + nh;
                    z[g] = Z0[r * 66 + nh] + Z1[r * 66 + nh]
                         + Z0[r * 66 + nl] + Z1[r * 66 + nl]
                         + Z0[(64 + r) * 66 + nh] + Z1[(64 + r) * 66 + nh];
                }
                const float cold = cb_base[(size_t)r * HID + hc];
                const float zf = z[0] + bias[hc]            + Wc[hc]            * cold;
                const float zi = z[1] + bias[HID + hc]      + Wc[HID + hc]      * cold;
                const float zg = z[2] + bias[2 * HID + hc]  + Wc[2 * HID + hc]  * cold;
                const float zo = z[3] + bias[3 * HID + hc]  + Wc[3 * HID + hc]  * cold;
                const float f  = sigm(zf);
                const float ii = sigm(zi);
                const float g  = tanhf(zg);
                const float o  = sigm(zo);
                const float cn = f * cold + ii * g;
                cb_base[(size_t)r * HID + hc] = cn;
                const float hv = o * tanhf(cn);
                __nv_bfloat16 hb = __float2bfloat16(hv);
                hhp_base[(size_t)r * HID + hc] = hb;
                hlp_base[(size_t)r * HID + hc] =
                    __float2bfloat16(hv - __bfloat162float(hb));
                if (out_base) out_base[(size_t)r * HID + hc] = hv;
            }
        }
        gbar();
    }

    // ---- final: sigmoid(outs @ finW + finb) -> out [4096, 256] ----
    {
        float *shA = (float *)smc;         // [32][68]
        float *shW = shA + 32 * 68;        // [64][68]
        const int row0 = bid * 32;
        const int r  = tid >> 3;           // 0..31
        const int dj = (tid & 7) * 8;      // 0..56
        #pragma unroll 1
        for (int ch = 0; ch < 4; ch++) {
            const int d0 = ch * 64;
            float f[8];
            #pragma unroll
            for (int j = 0; j < 8; j++) f[j] = 0.f;
            #pragma unroll 1
            for (int kb = 0; kb < HID; kb += 64) {
                __syncthreads();
                #pragma unroll
                for (int q = 0; q < 2; q++) {
                    const int quad = tid + q * NTHR;
                    const int ar = quad >> 4, akq = (quad & 15) * 4;
                    *(float4 *)&shA[ar * 68 + akq] =
                        *(const float4 *)&g_outs[(size_t)(row0 + ar) * HID + kb + akq];
                }
                #pragma unroll
                for (int q = 0; q < 4; q++) {
                    const int quad = tid + q * NTHR;
                    const int wr = quad >> 4, wq = (quad & 15) * 4;
                    *(float4 *)&shW[wr * 68 + wq] =
                        *(const float4 *)&p.finW[(size_t)(kb + wr) * DIN + d0 + wq];
                }
                __syncthreads();
                #pragma unroll 8
                for (int k = 0; k < 64; k++) {
                    const float a = shA[r * 68 + k];
                    const float4 w0 = *(const float4 *)&shW[k * 68 + dj];
                    const float4 w1 = *(const float4 *)&shW[k * 68 + dj + 4];
                    f[0] += a * w0.x; f[1] += a * w0.y;
                    f[2] += a * w0.z; f[3] += a * w0.w;
                    f[4] += a * w1.x; f[5] += a * w1.y;
                    f[6] += a * w1.z; f[7] += a * w1.w;
                }
            }
            float *op = p.out + (size_t)(row0 + r) * DIN + d0 + dj;
            #pragma unroll
            for (int j = 0; j < 8; j++)
                op[j] = sigm(f[j] + p.finb[d0 + dj + j]);
        }
    }
}

extern "C" void kernel_launch(void *const *d_in, const int *in_sizes, int n_in,
                              void *d_out, int out_size) {
    (void)in_sizes; (void)n_in; (void)out_size;
    Params p;
    p.x    = (const float *)d_in[0];
    p.eWx0 = (const float *)d_in[1];
    p.eWh0 = (const float *)d_in[2];
    p.eWc0 = (const float *)d_in[3];
    p.eb0  = (const float *)d_in[4];
    p.eWx  = (const float *)d_in[5];
    p.eWh  = (const float *)d_in[6];
    p.eWc  = (const float *)d_in[7];
    p.eb   = (const float *)d_in[8];
    p.dWx  = (const float *)d_in[9];
    p.dWh  = (const float *)d_in[10];
    p.dWc  = (const float *)d_in[11];
    p.db   = (const float *)d_in[12];
    p.finW = (const float *)d_in[13];
    p.finb = (const float *)d_in[14];
    p.h0   = (const float *)d_in[15];
    p.c0   = (const float *)d_in[16];
    p.out  = (float *)d_out;

    conv_kernel<<<23744, 256>>>(p);
    cudaFuncSetAttribute(lstm_kernel,
                         cudaFuncAttributeMaxDynamicSharedMemorySize, SMEM_REQ);
    lstm_kernel<<<GRID, NTHR, SMEM_REQ>>>(p);
}